// round 14
// baseline (speedup 1.0000x reference)
#include <cuda_runtime.h>
#include <cuda_bf16.h>
#include <cstdint>

#define NN 6400
#define CC 64
#define CP 128          // augmented K: [hi | lo] bf16
#define HH 80
#define NBAND 50        // 128-row bands
#define NSPLITB 25      // kB column splits; each CTA owns 2 adjacent tiles
#define TILE_BYTES 32768
#define SQRT_LOG2E 1.2011224087864498f

// kA dynamic smem: sA (32KB) + sB (32KB)
#define SMEM_BYTES_A 65536
// kB dynamic smem: sA (32KB) + sB0 (32KB) + sB1 (32KB)
#define SB0_OFF 32768
#define SB1_OFF 65536
#define SMEM_BYTES_B 98304

// augmented bf16 operand matrix P = [bf16(x') | bf16(x' - bf16(x'))] with
// x' = x * sqrt(log2 e)  (logits come out in log2 domain -> ex2 not exp).
// stored PRE-SWIZZLED: 16B chunk c of row r lives at chunk (c ^ (r&7)).
__device__ __nv_bfloat16 g_P[(size_t)NN * CP];
__device__ float g_MS[NBAND][NN];     // per-(slot,row) partial sum of ex2
__device__ float g_M[NN];             // per-row shift = ||x'||^2 (log2-domain)
__device__ float d_E[HH];             // exp(-d^2/2)
__device__ float d_S1[HH];            // sum_r E[|t-r|]

// ---------------------------------------------------------------------------
__device__ __forceinline__ float ex2f(float x) {
    float r; asm("ex2.approx.f32 %0, %1;" : "=f"(r) : "f"(x)); return r;
}

__device__ __forceinline__ void mma16816(float* c, const uint32_t* a,
                                         const uint32_t* b) {
    asm volatile(
        "mma.sync.aligned.m16n8k16.row.col.f32.bf16.bf16.f32 "
        "{%0,%1,%2,%3}, {%4,%5,%6,%7}, {%8,%9}, {%0,%1,%2,%3};"
        : "+f"(c[0]), "+f"(c[1]), "+f"(c[2]), "+f"(c[3])
        : "r"(a[0]), "r"(a[1]), "r"(a[2]), "r"(a[3]),
          "r"(b[0]), "r"(b[1]));
}

__device__ __forceinline__ void ldsm4(uint32_t* r, uint32_t addr) {
    asm volatile(
        "ldmatrix.sync.aligned.m8n8.x4.shared.b16 {%0,%1,%2,%3}, [%4];"
        : "=r"(r[0]), "=r"(r[1]), "=r"(r[2]), "=r"(r[3]) : "r"(addr));
}

__device__ __forceinline__ void mbar_init(uint32_t a, uint32_t cnt) {
    asm volatile("mbarrier.init.shared.b64 [%0], %1;" :: "r"(a), "r"(cnt) : "memory");
}
__device__ __forceinline__ void mbar_expect(uint32_t a, uint32_t bytes) {
    asm volatile("mbarrier.arrive.expect_tx.shared.b64 _, [%0], %1;"
                 :: "r"(a), "r"(bytes) : "memory");
}
__device__ __forceinline__ void mbar_wait(uint32_t a) {
    uint32_t done = 0;
    while (!done)
        asm volatile(
            "{ .reg .pred p; mbarrier.try_wait.parity.shared::cta.b64 p, [%1], %2;"
            " selp.b32 %0, 1, 0, p; }"
            : "=r"(done) : "r"(a), "r"(0) : "memory");
}
// one-instruction 32KB tile copy: global (contiguous, pre-swizzled) -> smem
__device__ __forceinline__ void bulk_g2s(uint32_t dst, const void* src,
                                         uint32_t bytes, uint32_t mbar) {
    asm volatile(
        "cp.async.bulk.shared::cta.global.mbarrier::complete_tx::bytes "
        "[%0], [%1], %2, [%3];"
        :: "r"(dst), "l"(src), "r"(bytes), "r"(mbar) : "memory");
}

// full-K (8 t-steps) mma over resident sA + one sB buffer (swizzled layout)
__device__ __forceinline__ void mma_tile(float acc[2][8][4],
                                         uint32_t abase0, uint32_t abase1,
                                         const uint32_t* bbase, uint32_t bbuf,
                                         int c0a, int c0b, int lr) {
    #pragma unroll
    for (int t = 0; t < 8; t++) {
        uint32_t ca = (uint32_t)((((t << 1) | c0a) ^ lr) << 4);
        uint32_t cb = (uint32_t)((((t << 1) | c0b) ^ lr) << 4);
        uint32_t afr[2][4];
        ldsm4(afr[0], abase0 + ca);
        ldsm4(afr[1], abase1 + ca);
        uint32_t bf[16];
        #pragma unroll
        for (int q = 0; q < 4; q++)
            ldsm4(&bf[q * 4], bbuf + bbase[q] + cb);
        #pragma unroll
        for (int mt = 0; mt < 2; mt++)
            #pragma unroll
            for (int nt = 0; nt < 8; nt++)
                mma16816(acc[mt][nt], afr[mt], &bf[nt * 2]);
    }
}

// ---------------------------------------------------------------------------
// kprep: build P pre-swizzled + scaled; compute g_M = ||x'||^2 per row;
// block 0 also builds Ad tables (E, S1).
// ---------------------------------------------------------------------------
__global__ __launch_bounds__(256) void kprep(const float* __restrict__ X) {
    int t = blockIdx.x * 256 + threadIdx.x;
    int row = t >> 3;
    int c   = t & 7;
    const float4* src = reinterpret_cast<const float4*>(
        X + (size_t)row * CC + c * 8);
    float4 v0 = src[0];
    float4 v1 = src[1];

    float xs[8] = {v0.x, v0.y, v0.z, v0.w, v1.x, v1.y, v1.z, v1.w};
    __nv_bfloat16 h[8], l[8];
    float nrm = 0.0f;
    #pragma unroll
    for (int i = 0; i < 8; i++) {
        float x = xs[i] * SQRT_LOG2E;
        nrm += x * x;
        __nv_bfloat16 hh = __float2bfloat16_rn(x);
        h[i] = hh;
        l[i] = __float2bfloat16_rn(x - __bfloat162float(hh));
    }
    // row-norm reduce across the 8 lanes of this row
    nrm += __shfl_xor_sync(0xFFFFFFFFu, nrm, 1);
    nrm += __shfl_xor_sync(0xFFFFFFFFu, nrm, 2);
    nrm += __shfl_xor_sync(0xFFFFFFFFu, nrm, 4);
    if (c == 0) g_M[row] = nrm;

    uint32_t off = (uint32_t)row * 256 + (uint32_t)((c ^ (row & 7)) * 16);
    char* base = reinterpret_cast<char*>(g_P);
    *reinterpret_cast<uint4*>(base + off)       = *reinterpret_cast<uint4*>(h);
    *reinterpret_cast<uint4*>(base + off + 128) = *reinterpret_cast<uint4*>(l);

    if (blockIdx.x == 0 && threadIdx.x < HH) {
        int tt = threadIdx.x;
        d_E[tt] = __expf(-0.5f * (float)(tt * tt));
        float s = 0.0f;
        #pragma unroll 8
        for (int r = 0; r < HH; r++) {
            int d = tt - r;
            s += __expf(-0.5f * (float)(d * d));
        }
        d_S1[tt] = s;
    }
}

// ---------------------------------------------------------------------------
// kA: pass A over the UPPER TRIANGLE of the symmetric exp matrix only.
// Tile (bi, bj), bi <= bj: one 128x128 GEMM yields
//   row-partials  (shift m_row) -> g_MS[bj][bi-band rows]
//   col-partials  (shift m_col) -> g_MS[bi][bj-band cols]   (bi != bj only)
// Every g_MS slot is written exactly once; band b collects slots 0..49.
// ---------------------------------------------------------------------------
__global__ __launch_bounds__(256, 2) void kA() {
    const int bi = blockIdx.y;
    const int bj = blockIdx.x;
    if (bj < bi) return;                 // lower triangle: exit immediately

    extern __shared__ __nv_bfloat16 smem[];
    __shared__ float sZ[2][128];
    __shared__ float sColW[4][128];
    __shared__ alignas(8) uint64_t mbar_s[2];

    const int tid  = threadIdx.x;
    const int lane = tid & 31;
    const int wid  = tid >> 5;
    const int warpM = wid & 3;
    const int warpN = wid >> 2;
    const int g  = lane >> 2;
    const int tg = lane & 3;
    const int lr = lane & 7;
    const int r0 = bi * 128;
    const int c0 = bj * 128;
    const bool offdiag = (bi != bj);

    uint32_t s_u = (uint32_t)__cvta_generic_to_shared(smem);
    const uint32_t sa_b = s_u;
    const uint32_t sb_buf = s_u + 32768;
    uint32_t mb_u = (uint32_t)__cvta_generic_to_shared(mbar_s);

    // LDSM lane row-bases (swizzled layout: row stride 256B)
    const int c0a = lane >> 4;
    const int c0b = (lane >> 3) & 1;
    uint32_t abase0, abase1, bbase[4];
    {
        int rA0 = warpM * 32 + 0  + ((lane >> 3) & 1) * 8 + lr;
        int rA1 = warpM * 32 + 16 + ((lane >> 3) & 1) * 8 + lr;
        abase0 = sa_b + rA0 * 256;
        abase1 = sa_b + rA1 * 256;
        #pragma unroll
        for (int q = 0; q < 4; q++) {
            int n = warpN * 64 + (q * 2 + (lane >> 4)) * 8 + lr;
            bbase[q] = (uint32_t)(n * 256);
        }
    }

    // per-slot row shift
    float pm[4];
    #pragma unroll
    for (int s = 0; s < 4; s++) {
        int row = r0 + warpM * 32 + (s >> 1) * 16 + (s & 1) * 8 + g;
        pm[s] = g_M[row];
    }

    if (tid == 0) {
        mbar_init(mb_u, 1);
        mbar_init(mb_u + 8, 1);
    }
    __syncthreads();

    const char* gp = reinterpret_cast<const char*>(g_P);
    if (tid == 0) {
        mbar_expect(mb_u, TILE_BYTES);
        bulk_g2s(sa_b, gp + (size_t)r0 * 256, TILE_BYTES, mb_u);
        mbar_expect(mb_u + 8, TILE_BYTES);
        bulk_g2s(sb_buf, gp + (size_t)c0 * 256, TILE_BYTES, mb_u + 8);
    }

    // column shifts for this thread's 16 columns (overlaps the copies)
    float pmc[8][2];
    if (offdiag) {
        #pragma unroll
        for (int nt = 0; nt < 8; nt++) {
            int colb = c0 + warpN * 64 + nt * 8 + tg * 2;
            pmc[nt][0] = g_M[colb];
            pmc[nt][1] = g_M[colb + 1];
        }
    }

    mbar_wait(mb_u);
    mbar_wait(mb_u + 8);

    float acc[2][8][4];
    #pragma unroll
    for (int mt = 0; mt < 2; mt++)
        #pragma unroll
        for (int nt = 0; nt < 8; nt++)
            #pragma unroll
            for (int i = 0; i < 4; i++)
                acc[mt][nt][i] = 0.0f;

    mma_tile(acc, abase0, abase1, bbase, sb_buf, c0a, c0b, lr);

    // ---- row-partial sums: ex2(v - m_row) ----
    float s_run[4];
    #pragma unroll
    for (int s = 0; s < 4; s++) {
        const int mt = s >> 1, h2 = (s & 1) * 2;
        float ssum = 0.0f;
        #pragma unroll
        for (int nt = 0; nt < 8; nt++)
            ssum += ex2f(acc[mt][nt][h2] - pm[s]) +
                    ex2f(acc[mt][nt][h2 + 1] - pm[s]);
        s_run[s] = ssum;
    }
    #pragma unroll
    for (int s = 0; s < 4; s++) {
        s_run[s] += __shfl_xor_sync(0xFFFFFFFFu, s_run[s], 1);
        s_run[s] += __shfl_xor_sync(0xFFFFFFFFu, s_run[s], 2);
    }
    if (tg == 0) {
        #pragma unroll
        for (int s = 0; s < 4; s++) {
            int rl = warpM * 32 + (s >> 1) * 16 + (s & 1) * 8 + g;
            sZ[warpN][rl] = s_run[s];
        }
    }

    // ---- col-partial sums: ex2(v - m_col), off-diagonal tiles only ----
    if (offdiag) {
        float colp[8][2];
        #pragma unroll
        for (int nt = 0; nt < 8; nt++) {
            #pragma unroll
            for (int c = 0; c < 2; c++) {
                colp[nt][c] = ex2f(acc[0][nt][c]     - pmc[nt][c]) +
                              ex2f(acc[0][nt][c + 2] - pmc[nt][c]) +
                              ex2f(acc[1][nt][c]     - pmc[nt][c]) +
                              ex2f(acc[1][nt][c + 2] - pmc[nt][c]);
            }
        }
        // reduce over the 8 g-lanes (offsets 4, 8, 16)
        #pragma unroll
        for (int off = 4; off <= 16; off <<= 1)
            #pragma unroll
            for (int nt = 0; nt < 8; nt++) {
                #pragma unroll
                for (int c = 0; c < 2; c++)
                    colp[nt][c] += __shfl_xor_sync(0xFFFFFFFFu, colp[nt][c], off);
            }
        if (g == 0) {
            #pragma unroll
            for (int nt = 0; nt < 8; nt++) {
                int cl = warpN * 64 + nt * 8 + tg * 2;
                sColW[warpM][cl]     = colp[nt][0];
                sColW[warpM][cl + 1] = colp[nt][1];
            }
        }
    }
    __syncthreads();

    if (tid < 128) {
        g_MS[bj][r0 + tid] = sZ[0][tid] + sZ[1][tid];
        if (offdiag)
            g_MS[bi][c0 + tid] = sColW[0][tid] + sColW[1][tid] +
                                 sColW[2][tid] + sColW[3][tid];
    }
}

// ---------------------------------------------------------------------------
// kB: pass B — 2 column tiles per CTA, all buffers loaded up front; computes
// Z inline from the 50 partial slots (kms deleted); fused softmax finalize +
// threshold, streaming stores.
// ---------------------------------------------------------------------------
__global__ __launch_bounds__(256, 2) void kB(float* __restrict__ As) {
    extern __shared__ __nv_bfloat16 smem[];
    __shared__ alignas(8) uint64_t mbar_s[3];

    const int tid  = threadIdx.x;
    const int lane = tid & 31;
    const int wid  = tid >> 5;
    const int warpM = wid & 3;
    const int warpN = wid >> 2;
    const int g  = lane >> 2;
    const int tg = lane & 3;
    const int lr = lane & 7;
    const int r0 = blockIdx.y * 128;
    const int split = blockIdx.x;

    uint32_t s_u = (uint32_t)__cvta_generic_to_shared(smem);
    const uint32_t sa_b = s_u;
    const uint32_t sb_b[2] = { s_u + SB0_OFF, s_u + SB1_OFF };
    uint32_t mb_u = (uint32_t)__cvta_generic_to_shared(mbar_s);

    const int c0a = lane >> 4;
    const int c0b = (lane >> 3) & 1;
    uint32_t abase0, abase1, bbase[4];
    {
        int rA0 = warpM * 32 + 0  + ((lane >> 3) & 1) * 8 + lr;
        int rA1 = warpM * 32 + 16 + ((lane >> 3) & 1) * 8 + lr;
        abase0 = sa_b + rA0 * 256;
        abase1 = sa_b + rA1 * 256;
        #pragma unroll
        for (int q = 0; q < 4; q++) {
            int n = warpN * 64 + (q * 2 + (lane >> 4)) * 8 + lr;
            bbase[q] = (uint32_t)(n * 256);
        }
    }

    if (tid == 0) {
        mbar_init(mb_u, 1);
        mbar_init(mb_u + 8, 1);
        mbar_init(mb_u + 16, 1);
    }
    __syncthreads();

    const char* gp = reinterpret_cast<const char*>(g_P);
    if (tid == 0) {
        mbar_expect(mb_u, TILE_BYTES);
        bulk_g2s(sa_b, gp + (size_t)r0 * 256, TILE_BYTES, mb_u);
        mbar_expect(mb_u + 8, TILE_BYTES);
        bulk_g2s(sb_b[0], gp + (size_t)(split * 256) * 256, TILE_BYTES, mb_u + 8);
        mbar_expect(mb_u + 16, TILE_BYTES);
        bulk_g2s(sb_b[1], gp + (size_t)(split * 256 + 128) * 256, TILE_BYTES, mb_u + 16);
    }

    // per-slot softmax params; Z assembled from the 50 partial slots.
    // (overlaps with the bulk copies; g_MS is L2-resident, 1.28 MB)
    int rowv[4];
    float Zacc[4] = {0.0f, 0.0f, 0.0f, 0.0f};
    #pragma unroll
    for (int s = 0; s < 4; s++)
        rowv[s] = r0 + warpM * 32 + (s >> 1) * 16 + (s & 1) * 8 + g;
    #pragma unroll 5
    for (int k = 0; k < NBAND; k++) {
        #pragma unroll
        for (int s = 0; s < 4; s++)
            Zacc[s] += __ldg(&g_MS[k][rowv[s]]);
    }
    float pm[4], piz[4], pth[4];
    #pragma unroll
    for (int s = 0; s < 4; s++) {
        pm[s]  = g_M[rowv[s]];
        piz[s] = 1.0f / Zacc[s];
        pth[s] = Zacc[s] * (1.0f / (float)NN);
    }

    mbar_wait(mb_u);   // sA ready

    #pragma unroll
    for (int li = 0; li < 2; li++) {
        mbar_wait(mb_u + (li + 1) * 8);

        float acc[2][8][4];
        #pragma unroll
        for (int mt = 0; mt < 2; mt++)
            #pragma unroll
            for (int nt = 0; nt < 8; nt++)
                #pragma unroll
                for (int i = 0; i < 4; i++)
                    acc[mt][nt][i] = 0.0f;

        mma_tile(acc, abase0, abase1, bbase, sb_b[li], c0a, c0b, lr);

        // fused softmax epilogue + streaming store for this column tile
        const int c0 = (split * 2 + li) * 128;
        #pragma unroll
        for (int mt = 0; mt < 2; mt++) {
            const int s0 = mt * 2, s1 = mt * 2 + 1;
            #pragma unroll
            for (int nt = 0; nt < 8; nt++) {
                int row = r0 + warpM * 32 + mt * 16 + g;
                int col = c0 + warpN * 64 + nt * 8 + tg * 2;
                float e0 = ex2f(acc[mt][nt][0] - pm[s0]);
                float e1 = ex2f(acc[mt][nt][1] - pm[s0]);
                float e2 = ex2f(acc[mt][nt][2] - pm[s1]);
                float e3 = ex2f(acc[mt][nt][3] - pm[s1]);
                float2 v0, v1;
                v0.x = (e0 < pth[s0]) ? 0.0f : e0 * piz[s0];
                v0.y = (e1 < pth[s0]) ? 0.0f : e1 * piz[s0];
                v1.x = (e2 < pth[s1]) ? 0.0f : e2 * piz[s1];
                v1.y = (e3 < pth[s1]) ? 0.0f : e3 * piz[s1];
                __stcs(reinterpret_cast<float2*>(&As[(size_t)row * NN + col]), v0);
                __stcs(reinterpret_cast<float2*>(&As[(size_t)(row + 8) * NN + col]), v1);
            }
        }
    }
}

// ---------------------------------------------------------------------------
// k3: analytic Ad, one row per CTA via Kronecker of two 80-vectors.
// Launched on a side stream, overlapping kA/kB.
// ---------------------------------------------------------------------------
__global__ __launch_bounds__(256) void k3_ad(float* __restrict__ Ad) {
    __shared__ float erinv[HH];
    __shared__ float4 ec4[HH / 4];

    const int tid = threadIdx.x;
    const int i   = blockIdx.x;
    const int ri  = i / HH;
    const int ci  = i - ri * HH;

    const float inv = 1.0f / (__ldg(&d_S1[ri]) * __ldg(&d_S1[ci]) - 1.0f);
    if (tid < HH) {
        int dr = ri - tid; dr = dr < 0 ? -dr : dr;
        int dc = ci - tid; dc = dc < 0 ? -dc : dc;
        erinv[tid] = __ldg(&d_E[dr]) * inv;
        reinterpret_cast<float*>(ec4)[tid] = __ldg(&d_E[dc]);
    }
    __syncthreads();

    float* rowp = Ad + (size_t)i * NN;
    for (int q = tid; q < NN / 4; q += 256) {
        int rj = q / 20;          // 20 float4 per 80-col block
        int cq = q - rj * 20;
        float er = erinv[rj];
        float4 e = ec4[cq];
        float4 o;
        o.x = er * e.x;
        o.y = er * e.y;
        o.z = er * e.z;
        o.w = er * e.w;
        __stcs(reinterpret_cast<float4*>(rowp) + q, o);
    }
    __syncthreads();
    if (tid == 0) rowp[i] = 0.0f;
}

// ---------------------------------------------------------------------------
extern "C" void kernel_launch(void* const* d_in, const int* in_sizes, int n_in,
                              void* d_out, int out_size) {
    const float* X = (const float*)d_in[0];
    float* Ad = (float*)d_out;                       // first N*N floats
    float* As = (float*)d_out + (size_t)NN * NN;     // second N*N floats

    static cudaStream_t s_side = nullptr;
    static cudaEvent_t ev_fork = nullptr, ev_join = nullptr;
    if (!s_side) {
        cudaStreamCreateWithFlags(&s_side, cudaStreamNonBlocking);
        cudaEventCreateWithFlags(&ev_fork, cudaEventDisableTiming);
        cudaEventCreateWithFlags(&ev_join, cudaEventDisableTiming);
        cudaFuncSetAttribute(kA, cudaFuncAttributeMaxDynamicSharedMemorySize, SMEM_BYTES_A);
        cudaFuncSetAttribute(kB, cudaFuncAttributeMaxDynamicSharedMemorySize, SMEM_BYTES_B);
    }

    kprep<<<200, 256>>>(X);

    // fork: k3_ad runs on the side stream, overlapping kA/kB
    cudaEventRecord(ev_fork, 0);
    cudaStreamWaitEvent(s_side, ev_fork, 0);
    k3_ad<<<NN, 256, 0, s_side>>>(Ad);
    cudaEventRecord(ev_join, s_side);

    kA<<<dim3(NBAND, NBAND), 256, SMEM_BYTES_A>>>();   // upper triangle active
    kB<<<dim3(NSPLITB, NBAND), 256, SMEM_BYTES_B>>>(As);

    // join
    cudaStreamWaitEvent(0, ev_join, 0);
}

// round 17
// speedup vs baseline: 1.1034x; 1.1034x over previous
#include <cuda_runtime.h>
#include <cuda_bf16.h>
#include <cstdint>

#define NN 6400
#define CC 64
#define CP 128          // augmented K: [hi | lo] bf16
#define HH 80
#define NBAND 50        // 128-row bands
#define NSPLITB 25      // kB column splits; each CTA owns 2 adjacent tiles
#define TILE_BYTES 32768
#define SQRT_LOG2E 1.2011224087864498f

// kA dynamic smem: sA (32KB) + sB (32KB)
#define SMEM_BYTES_A 65536
// kB dynamic smem: sA (32KB) + sB0 (32KB) + sB1 (32KB)
#define SB0_OFF 32768
#define SB1_OFF 65536
#define SMEM_BYTES_B 98304

// augmented bf16 operand matrix P = [bf16(x') | bf16(x' - bf16(x'))] with
// x' = x * sqrt(log2 e)  (logits come out in log2 domain -> ex2 not exp).
// stored PRE-SWIZZLED: 16B chunk c of row r lives at chunk (c ^ (r&7)).
__device__ __nv_bfloat16 g_P[(size_t)NN * CP];
__device__ float g_MS[NBAND][NN];     // per-(slot,row) partial sum of ex2
__device__ float g_M[NN];             // per-row shift = ||x'||^2 (log2-domain)
__device__ float g_Z[NN];
__device__ float d_E[HH];             // exp(-d^2/2)
__device__ float d_S1[HH];            // sum_r E[|t-r|]

// ---------------------------------------------------------------------------
__device__ __forceinline__ float ex2f(float x) {
    float r; asm("ex2.approx.f32 %0, %1;" : "=f"(r) : "f"(x)); return r;
}

__device__ __forceinline__ void mma16816(float* c, const uint32_t* a,
                                         const uint32_t* b) {
    asm volatile(
        "mma.sync.aligned.m16n8k16.row.col.f32.bf16.bf16.f32 "
        "{%0,%1,%2,%3}, {%4,%5,%6,%7}, {%8,%9}, {%0,%1,%2,%3};"
        : "+f"(c[0]), "+f"(c[1]), "+f"(c[2]), "+f"(c[3])
        : "r"(a[0]), "r"(a[1]), "r"(a[2]), "r"(a[3]),
          "r"(b[0]), "r"(b[1]));
}

__device__ __forceinline__ void ldsm4(uint32_t* r, uint32_t addr) {
    asm volatile(
        "ldmatrix.sync.aligned.m8n8.x4.shared.b16 {%0,%1,%2,%3}, [%4];"
        : "=r"(r[0]), "=r"(r[1]), "=r"(r[2]), "=r"(r[3]) : "r"(addr));
}

__device__ __forceinline__ void mbar_init(uint32_t a, uint32_t cnt) {
    asm volatile("mbarrier.init.shared.b64 [%0], %1;" :: "r"(a), "r"(cnt) : "memory");
}
__device__ __forceinline__ void mbar_expect(uint32_t a, uint32_t bytes) {
    asm volatile("mbarrier.arrive.expect_tx.shared.b64 _, [%0], %1;"
                 :: "r"(a), "r"(bytes) : "memory");
}
__device__ __forceinline__ void mbar_wait(uint32_t a) {
    uint32_t done = 0;
    while (!done)
        asm volatile(
            "{ .reg .pred p; mbarrier.try_wait.parity.shared::cta.b64 p, [%1], %2;"
            " selp.b32 %0, 1, 0, p; }"
            : "=r"(done) : "r"(a), "r"(0) : "memory");
}
// one-instruction 32KB tile copy: global (contiguous, pre-swizzled) -> smem
__device__ __forceinline__ void bulk_g2s(uint32_t dst, const void* src,
                                         uint32_t bytes, uint32_t mbar) {
    asm volatile(
        "cp.async.bulk.shared::cta.global.mbarrier::complete_tx::bytes "
        "[%0], [%1], %2, [%3];"
        :: "r"(dst), "l"(src), "r"(bytes), "r"(mbar) : "memory");
}

// full-K (8 t-steps) mma over resident sA + one sB buffer (swizzled layout)
__device__ __forceinline__ void mma_tile(float acc[2][8][4],
                                         uint32_t abase0, uint32_t abase1,
                                         const uint32_t* bbase, uint32_t bbuf,
                                         int c0a, int c0b, int lr) {
    #pragma unroll
    for (int t = 0; t < 8; t++) {
        uint32_t ca = (uint32_t)((((t << 1) | c0a) ^ lr) << 4);
        uint32_t cb = (uint32_t)((((t << 1) | c0b) ^ lr) << 4);
        uint32_t afr[2][4];
        ldsm4(afr[0], abase0 + ca);
        ldsm4(afr[1], abase1 + ca);
        uint32_t bf[16];
        #pragma unroll
        for (int q = 0; q < 4; q++)
            ldsm4(&bf[q * 4], bbuf + bbase[q] + cb);
        #pragma unroll
        for (int mt = 0; mt < 2; mt++)
            #pragma unroll
            for (int nt = 0; nt < 8; nt++)
                mma16816(acc[mt][nt], afr[mt], &bf[nt * 2]);
    }
}

// ---------------------------------------------------------------------------
// kprep: build P pre-swizzled + scaled; compute g_M = ||x'||^2 per row;
// block 0 also builds Ad tables (E, S1).
// ---------------------------------------------------------------------------
__global__ __launch_bounds__(256) void kprep(const float* __restrict__ X) {
    int t = blockIdx.x * 256 + threadIdx.x;
    int row = t >> 3;
    int c   = t & 7;
    const float4* src = reinterpret_cast<const float4*>(
        X + (size_t)row * CC + c * 8);
    float4 v0 = src[0];
    float4 v1 = src[1];

    float xs[8] = {v0.x, v0.y, v0.z, v0.w, v1.x, v1.y, v1.z, v1.w};
    __nv_bfloat16 h[8], l[8];
    float nrm = 0.0f;
    #pragma unroll
    for (int i = 0; i < 8; i++) {
        float x = xs[i] * SQRT_LOG2E;
        nrm += x * x;
        __nv_bfloat16 hh = __float2bfloat16_rn(x);
        h[i] = hh;
        l[i] = __float2bfloat16_rn(x - __bfloat162float(hh));
    }
    // row-norm reduce across the 8 lanes of this row
    nrm += __shfl_xor_sync(0xFFFFFFFFu, nrm, 1);
    nrm += __shfl_xor_sync(0xFFFFFFFFu, nrm, 2);
    nrm += __shfl_xor_sync(0xFFFFFFFFu, nrm, 4);
    if (c == 0) g_M[row] = nrm;

    uint32_t off = (uint32_t)row * 256 + (uint32_t)((c ^ (row & 7)) * 16);
    char* base = reinterpret_cast<char*>(g_P);
    *reinterpret_cast<uint4*>(base + off)       = *reinterpret_cast<uint4*>(h);
    *reinterpret_cast<uint4*>(base + off + 128) = *reinterpret_cast<uint4*>(l);

    if (blockIdx.x == 0 && threadIdx.x < HH) {
        int tt = threadIdx.x;
        d_E[tt] = __expf(-0.5f * (float)(tt * tt));
        float s = 0.0f;
        #pragma unroll 8
        for (int r = 0; r < HH; r++) {
            int d = tt - r;
            s += __expf(-0.5f * (float)(d * d));
        }
        d_S1[tt] = s;
    }
}

// ---------------------------------------------------------------------------
// kA: pass A over the UPPER TRIANGLE of the symmetric exp matrix only.
// Tile (bi, bj), bi <= bj: one 128x128 GEMM yields
//   row-partials  (shift m_row) -> g_MS[bj][bi-band rows]
//   col-partials  (shift m_col) -> g_MS[bi][bj-band cols]   (bi != bj only)
// Every g_MS slot is written exactly once; band b collects slots 0..49.
// ---------------------------------------------------------------------------
__global__ __launch_bounds__(256, 2) void kA() {
    const int bi = blockIdx.y;
    const int bj = blockIdx.x;
    if (bj < bi) return;                 // lower triangle: exit immediately

    extern __shared__ __nv_bfloat16 smem[];
    __shared__ float sZ[2][128];
    __shared__ float sColW[4][128];
    __shared__ alignas(8) uint64_t mbar_s[2];

    const int tid  = threadIdx.x;
    const int lane = tid & 31;
    const int wid  = tid >> 5;
    const int warpM = wid & 3;
    const int warpN = wid >> 2;
    const int g  = lane >> 2;
    const int tg = lane & 3;
    const int lr = lane & 7;
    const int r0 = bi * 128;
    const int c0 = bj * 128;
    const bool offdiag = (bi != bj);

    uint32_t s_u = (uint32_t)__cvta_generic_to_shared(smem);
    const uint32_t sa_b = s_u;
    const uint32_t sb_buf = s_u + 32768;
    uint32_t mb_u = (uint32_t)__cvta_generic_to_shared(mbar_s);

    // LDSM lane row-bases (swizzled layout: row stride 256B)
    const int c0a = lane >> 4;
    const int c0b = (lane >> 3) & 1;
    uint32_t abase0, abase1, bbase[4];
    {
        int rA0 = warpM * 32 + 0  + ((lane >> 3) & 1) * 8 + lr;
        int rA1 = warpM * 32 + 16 + ((lane >> 3) & 1) * 8 + lr;
        abase0 = sa_b + rA0 * 256;
        abase1 = sa_b + rA1 * 256;
        #pragma unroll
        for (int q = 0; q < 4; q++) {
            int n = warpN * 64 + (q * 2 + (lane >> 4)) * 8 + lr;
            bbase[q] = (uint32_t)(n * 256);
        }
    }

    // per-slot row shift
    float pm[4];
    #pragma unroll
    for (int s = 0; s < 4; s++) {
        int row = r0 + warpM * 32 + (s >> 1) * 16 + (s & 1) * 8 + g;
        pm[s] = g_M[row];
    }

    if (tid == 0) {
        mbar_init(mb_u, 1);
        mbar_init(mb_u + 8, 1);
    }
    __syncthreads();

    const char* gp = reinterpret_cast<const char*>(g_P);
    if (tid == 0) {
        mbar_expect(mb_u, TILE_BYTES);
        bulk_g2s(sa_b, gp + (size_t)r0 * 256, TILE_BYTES, mb_u);
        mbar_expect(mb_u + 8, TILE_BYTES);
        bulk_g2s(sb_buf, gp + (size_t)c0 * 256, TILE_BYTES, mb_u + 8);
    }

    // column shifts for this thread's 16 columns (overlaps the copies)
    float pmc[8][2];
    if (offdiag) {
        #pragma unroll
        for (int nt = 0; nt < 8; nt++) {
            int colb = c0 + warpN * 64 + nt * 8 + tg * 2;
            pmc[nt][0] = g_M[colb];
            pmc[nt][1] = g_M[colb + 1];
        }
    }

    mbar_wait(mb_u);
    mbar_wait(mb_u + 8);

    float acc[2][8][4];
    #pragma unroll
    for (int mt = 0; mt < 2; mt++)
        #pragma unroll
        for (int nt = 0; nt < 8; nt++)
            #pragma unroll
            for (int i = 0; i < 4; i++)
                acc[mt][nt][i] = 0.0f;

    mma_tile(acc, abase0, abase1, bbase, sb_buf, c0a, c0b, lr);

    // ---- row-partial sums: ex2(v - m_row) ----
    float s_run[4];
    #pragma unroll
    for (int s = 0; s < 4; s++) {
        const int mt = s >> 1, h2 = (s & 1) * 2;
        float ssum = 0.0f;
        #pragma unroll
        for (int nt = 0; nt < 8; nt++)
            ssum += ex2f(acc[mt][nt][h2] - pm[s]) +
                    ex2f(acc[mt][nt][h2 + 1] - pm[s]);
        s_run[s] = ssum;
    }
    #pragma unroll
    for (int s = 0; s < 4; s++) {
        s_run[s] += __shfl_xor_sync(0xFFFFFFFFu, s_run[s], 1);
        s_run[s] += __shfl_xor_sync(0xFFFFFFFFu, s_run[s], 2);
    }
    if (tg == 0) {
        #pragma unroll
        for (int s = 0; s < 4; s++) {
            int rl = warpM * 32 + (s >> 1) * 16 + (s & 1) * 8 + g;
            sZ[warpN][rl] = s_run[s];
        }
    }

    // ---- col-partial sums: ex2(v - m_col), off-diagonal tiles only ----
    if (offdiag) {
        float colp[8][2];
        #pragma unroll
        for (int nt = 0; nt < 8; nt++) {
            #pragma unroll
            for (int c = 0; c < 2; c++) {
                colp[nt][c] = ex2f(acc[0][nt][c]     - pmc[nt][c]) +
                              ex2f(acc[0][nt][c + 2] - pmc[nt][c]) +
                              ex2f(acc[1][nt][c]     - pmc[nt][c]) +
                              ex2f(acc[1][nt][c + 2] - pmc[nt][c]);
            }
        }
        // reduce over the 8 g-lanes (offsets 4, 8, 16)
        #pragma unroll
        for (int off = 4; off <= 16; off <<= 1)
            #pragma unroll
            for (int nt = 0; nt < 8; nt++) {
                #pragma unroll
                for (int c = 0; c < 2; c++)
                    colp[nt][c] += __shfl_xor_sync(0xFFFFFFFFu, colp[nt][c], off);
            }
        if (g == 0) {
            #pragma unroll
            for (int nt = 0; nt < 8; nt++) {
                int cl = warpN * 64 + nt * 8 + tg * 2;
                sColW[warpM][cl]     = colp[nt][0];
                sColW[warpM][cl + 1] = colp[nt][1];
            }
        }
    }
    __syncthreads();

    if (tid < 128) {
        g_MS[bj][r0 + tid] = sZ[0][tid] + sZ[1][tid];
        if (offdiag)
            g_MS[bi][c0 + tid] = sColW[0][tid] + sColW[1][tid] +
                                 sColW[2][tid] + sColW[3][tid];
    }
}

// ---------------------------------------------------------------------------
// kms: merge the NBAND partial sums -> g_Z
// ---------------------------------------------------------------------------
__global__ __launch_bounds__(128) void kms() {
    int r = blockIdx.x * 128 + threadIdx.x;   // 50 blocks
    float S = 0.0f;
    #pragma unroll 10
    for (int i = 0; i < NBAND; i++) S += g_MS[i][r];
    g_Z[r] = S;
}

// ---------------------------------------------------------------------------
// kB: pass B — 2 column tiles per CTA, all buffers loaded up front; fused
// softmax finalize + threshold, streaming stores.
// ---------------------------------------------------------------------------
__global__ __launch_bounds__(256, 2) void kB(float* __restrict__ As) {
    extern __shared__ __nv_bfloat16 smem[];
    __shared__ alignas(8) uint64_t mbar_s[3];

    const int tid  = threadIdx.x;
    const int lane = tid & 31;
    const int wid  = tid >> 5;
    const int warpM = wid & 3;
    const int warpN = wid >> 2;
    const int g  = lane >> 2;
    const int tg = lane & 3;
    const int lr = lane & 7;
    const int r0 = blockIdx.y * 128;
    const int split = blockIdx.x;

    uint32_t s_u = (uint32_t)__cvta_generic_to_shared(smem);
    const uint32_t sa_b = s_u;
    const uint32_t sb_b[2] = { s_u + SB0_OFF, s_u + SB1_OFF };
    uint32_t mb_u = (uint32_t)__cvta_generic_to_shared(mbar_s);

    const int c0a = lane >> 4;
    const int c0b = (lane >> 3) & 1;
    uint32_t abase0, abase1, bbase[4];
    {
        int rA0 = warpM * 32 + 0  + ((lane >> 3) & 1) * 8 + lr;
        int rA1 = warpM * 32 + 16 + ((lane >> 3) & 1) * 8 + lr;
        abase0 = sa_b + rA0 * 256;
        abase1 = sa_b + rA1 * 256;
        #pragma unroll
        for (int q = 0; q < 4; q++) {
            int n = warpN * 64 + (q * 2 + (lane >> 4)) * 8 + lr;
            bbase[q] = (uint32_t)(n * 256);
        }
    }

    if (tid == 0) {
        mbar_init(mb_u, 1);
        mbar_init(mb_u + 8, 1);
        mbar_init(mb_u + 16, 1);
    }
    __syncthreads();

    const char* gp = reinterpret_cast<const char*>(g_P);
    if (tid == 0) {
        mbar_expect(mb_u, TILE_BYTES);
        bulk_g2s(sa_b, gp + (size_t)r0 * 256, TILE_BYTES, mb_u);
        mbar_expect(mb_u + 8, TILE_BYTES);
        bulk_g2s(sb_b[0], gp + (size_t)(split * 256) * 256, TILE_BYTES, mb_u + 8);
        mbar_expect(mb_u + 16, TILE_BYTES);
        bulk_g2s(sb_b[1], gp + (size_t)(split * 256 + 128) * 256, TILE_BYTES, mb_u + 16);
    }

    // per-slot softmax params (overlaps with bulk copies)
    float pm[4], piz[4], pth[4];
    #pragma unroll
    for (int s = 0; s < 4; s++) {
        int row = r0 + warpM * 32 + (s >> 1) * 16 + (s & 1) * 8 + g;
        float Z = g_Z[row];
        pm[s]  = g_M[row];
        piz[s] = 1.0f / Z;
        pth[s] = Z * (1.0f / (float)NN);
    }

    mbar_wait(mb_u);   // sA ready

    #pragma unroll
    for (int li = 0; li < 2; li++) {
        mbar_wait(mb_u + (li + 1) * 8);

        float acc[2][8][4];
        #pragma unroll
        for (int mt = 0; mt < 2; mt++)
            #pragma unroll
            for (int nt = 0; nt < 8; nt++)
                #pragma unroll
                for (int i = 0; i < 4; i++)
                    acc[mt][nt][i] = 0.0f;

        mma_tile(acc, abase0, abase1, bbase, sb_b[li], c0a, c0b, lr);

        // fused softmax epilogue + streaming store for this column tile
        const int c0 = (split * 2 + li) * 128;
        #pragma unroll
        for (int mt = 0; mt < 2; mt++) {
            const int s0 = mt * 2, s1 = mt * 2 + 1;
            #pragma unroll
            for (int nt = 0; nt < 8; nt++) {
                int row = r0 + warpM * 32 + mt * 16 + g;
                int col = c0 + warpN * 64 + nt * 8 + tg * 2;
                float e0 = ex2f(acc[mt][nt][0] - pm[s0]);
                float e1 = ex2f(acc[mt][nt][1] - pm[s0]);
                float e2 = ex2f(acc[mt][nt][2] - pm[s1]);
                float e3 = ex2f(acc[mt][nt][3] - pm[s1]);
                float2 v0, v1;
                v0.x = (e0 < pth[s0]) ? 0.0f : e0 * piz[s0];
                v0.y = (e1 < pth[s0]) ? 0.0f : e1 * piz[s0];
                v1.x = (e2 < pth[s1]) ? 0.0f : e2 * piz[s1];
                v1.y = (e3 < pth[s1]) ? 0.0f : e3 * piz[s1];
                __stcs(reinterpret_cast<float2*>(&As[(size_t)row * NN + col]), v0);
                __stcs(reinterpret_cast<float2*>(&As[(size_t)(row + 8) * NN + col]), v1);
            }
        }
    }
}

// ---------------------------------------------------------------------------
// k3: analytic Ad, one row per CTA via Kronecker of two 80-vectors.
// Launched on a side stream, overlapping kA/kms/kB.
// ---------------------------------------------------------------------------
__global__ __launch_bounds__(256) void k3_ad(float* __restrict__ Ad) {
    __shared__ float erinv[HH];
    __shared__ float4 ec4[HH / 4];

    const int tid = threadIdx.x;
    const int i   = blockIdx.x;
    const int ri  = i / HH;
    const int ci  = i - ri * HH;

    const float inv = 1.0f / (__ldg(&d_S1[ri]) * __ldg(&d_S1[ci]) - 1.0f);
    if (tid < HH) {
        int dr = ri - tid; dr = dr < 0 ? -dr : dr;
        int dc = ci - tid; dc = dc < 0 ? -dc : dc;
        erinv[tid] = __ldg(&d_E[dr]) * inv;
        reinterpret_cast<float*>(ec4)[tid] = __ldg(&d_E[dc]);
    }
    __syncthreads();

    float* rowp = Ad + (size_t)i * NN;
    for (int q = tid; q < NN / 4; q += 256) {
        int rj = q / 20;          // 20 float4 per 80-col block
        int cq = q - rj * 20;
        float er = erinv[rj];
        float4 e = ec4[cq];
        float4 o;
        o.x = er * e.x;
        o.y = er * e.y;
        o.z = er * e.z;
        o.w = er * e.w;
        __stcs(reinterpret_cast<float4*>(rowp) + q, o);
    }
    __syncthreads();
    if (tid == 0) rowp[i] = 0.0f;
}

// ---------------------------------------------------------------------------
extern "C" void kernel_launch(void* const* d_in, const int* in_sizes, int n_in,
                              void* d_out, int out_size) {
    const float* X = (const float*)d_in[0];
    float* Ad = (float*)d_out;                       // first N*N floats
    float* As = (float*)d_out + (size_t)NN * NN;     // second N*N floats

    static cudaStream_t s_side = nullptr;
    static cudaEvent_t ev_fork = nullptr, ev_join = nullptr;
    if (!s_side) {
        cudaStreamCreateWithFlags(&s_side, cudaStreamNonBlocking);
        cudaEventCreateWithFlags(&ev_fork, cudaEventDisableTiming);
        cudaEventCreateWithFlags(&ev_join, cudaEventDisableTiming);
        cudaFuncSetAttribute(kA, cudaFuncAttributeMaxDynamicSharedMemorySize, SMEM_BYTES_A);
        cudaFuncSetAttribute(kB, cudaFuncAttributeMaxDynamicSharedMemorySize, SMEM_BYTES_B);
    }

    kprep<<<200, 256>>>(X);

    // fork: k3_ad runs on the side stream, overlapping kA/kms/kB
    cudaEventRecord(ev_fork, 0);
    cudaStreamWaitEvent(s_side, ev_fork, 0);
    k3_ad<<<NN, 256, 0, s_side>>>(Ad);
    cudaEventRecord(ev_join, s_side);

    kA<<<dim3(NBAND, NBAND), 256, SMEM_BYTES_A>>>();   // upper triangle active
    kms<<<NN / 128, 128>>>();
    kB<<<dim3(NSPLITB, NBAND), 256, SMEM_BYTES_B>>>(As);

    // join
    cudaStreamWaitEvent(0, ev_join, 0);
}